// round 1
// baseline (speedup 1.0000x reference)
#include <cuda_runtime.h>
#include <cuda_bf16.h>
#include <math.h>

// Problem dims (fixed by the dataset):
//   T=8192, E=8, D_IN=1024, D_H=4096, D_OUT=1024, TOP_K=2
#define E_EXP   8
#define D_IN    1024
#define D_H     4096
#define D_OUT   1024
#define T_MAX   8192
#define BM      8      // tokens per FFN block
#define HC      256    // h-chunk width (== blockDim.x)
#define NTHR    256

// ---------------- device scratch (allocation-free) ----------------
__device__ int   g_counts[E_EXP];
__device__ int   g_btok[E_EXP * T_MAX];
__device__ float g_bw  [E_EXP * T_MAX];

// ---------------- zero counters ----------------
__global__ void zero_counts_kernel() {
    if (threadIdx.x < E_EXP) g_counts[threadIdx.x] = 0;
}

// ---------------- gate: logits -> top-2 -> softmax -> buckets ----------------
__global__ void gate_kernel(const float* __restrict__ x,
                            const float* __restrict__ Wg,
                            const float* __restrict__ bg,
                            int T) {
    int gwarp = (blockIdx.x * blockDim.x + threadIdx.x) >> 5;
    int lane  = threadIdx.x & 31;
    if (gwarp >= T) return;

    const float* xr = x + (size_t)gwarp * D_IN;

    // each lane loads 32 strided elements of the token's x row
    float xv[32];
#pragma unroll
    for (int k = 0; k < 32; k++) xv[k] = xr[lane + 32 * k];

    float logit[E_EXP];
#pragma unroll
    for (int e = 0; e < E_EXP; e++) {
        float s = 0.f;
#pragma unroll
        for (int k = 0; k < 32; k++) s += xv[k] * Wg[(size_t)(lane + 32 * k) * E_EXP + e];
#pragma unroll
        for (int off = 16; off; off >>= 1) s += __shfl_xor_sync(0xFFFFFFFFu, s, off);
        logit[e] = s + bg[e];
    }

    if (lane == 0) {
        // top-1 (strict > keeps lowest index on ties, matching lax.top_k)
        int i0 = 0; float v0 = logit[0];
#pragma unroll
        for (int e = 1; e < E_EXP; e++) if (logit[e] > v0) { v0 = logit[e]; i0 = e; }
        // top-2 excluding i0
        int i1 = -1; float v1 = -INFINITY;
#pragma unroll
        for (int e = 0; e < E_EXP; e++)
            if (e != i0 && logit[e] > v1) { v1 = logit[e]; i1 = e; }

        // softmax over {v0, v1}; v0 >= v1
        float e1 = expf(v1 - v0);
        float inv = 1.f / (1.f + e1);
        float w0 = inv;
        float w1 = e1 * inv;

        int s0 = atomicAdd(&g_counts[i0], 1);
        g_btok[i0 * T_MAX + s0] = gwarp;
        g_bw  [i0 * T_MAX + s0] = w0;
        int s1 = atomicAdd(&g_counts[i1], 1);
        g_btok[i1 * T_MAX + s1] = gwarp;
        g_bw  [i1 * T_MAX + s1] = w1;
    }
}

// ---------------- grouped FFN: per-expert two-layer MLP ----------------
// block = (expert e, tile m): BM tokens of expert e's bucket.
// h computed in chunks of HC columns, output accumulator kept in registers.
__global__ void __launch_bounds__(NTHR)
ffn_kernel(const float* __restrict__ x,
           const float* __restrict__ W1,
           const float* __restrict__ b1,
           const float* __restrict__ W2,
           const float* __restrict__ b2,
           float* __restrict__ out) {
    const int e = blockIdx.y;
    const int m = blockIdx.x;
    const int n = g_counts[e];
    if (m * BM >= n) return;

    __shared__ float xs[BM][D_IN];
    __shared__ float hs[BM][HC];

    const int tid = threadIdx.x;

    int   toks[BM];
    float wts [BM];
#pragma unroll
    for (int t = 0; t < BM; t++) {
        int slot = m * BM + t;
        int cs   = min(slot, n - 1);
        toks[t]  = g_btok[e * T_MAX + cs];
        wts [t]  = (slot < n) ? g_bw[e * T_MAX + cs] : 0.f;
    }

    // stage x rows for the BM tokens
#pragma unroll
    for (int t = 0; t < BM; t++) {
        const float* xr = x + (size_t)toks[t] * D_IN;
        for (int i = tid; i < D_IN; i += NTHR) xs[t][i] = xr[i];
    }
    __syncthreads();

    const float* W1e = W1 + (size_t)e * D_IN * D_H;
    const float* W2e = W2 + (size_t)e * D_H * D_OUT;

    // output accumulators: thread owns out-cols tid, tid+256, tid+512, tid+768
    float acc[BM][4];
#pragma unroll
    for (int c = 0; c < 4; c++) {
        float bb = b2[e * D_OUT + tid + 256 * c];
#pragma unroll
        for (int t = 0; t < BM; t++) acc[t][c] = bb;
    }

    for (int ch = 0; ch < D_H / HC; ch++) {
        // ---- layer 1: this thread owns h-column j for all BM tokens ----
        const int j = ch * HC + tid;
        float ha[BM];
        float bj = b1[e * D_H + j];
#pragma unroll
        for (int t = 0; t < BM; t++) ha[t] = bj;

        const float* w1p = W1e + j;
#pragma unroll 4
        for (int i = 0; i < D_IN; i++) {
            float w = w1p[(size_t)i * D_H];
#pragma unroll
            for (int t = 0; t < BM; t++) ha[t] += xs[t][i] * w;
        }

        __syncthreads();   // previous chunk's hs fully consumed
#pragma unroll
        for (int t = 0; t < BM; t++) hs[t][tid] = fmaxf(ha[t], 0.f);
        __syncthreads();

        // ---- layer 2: accumulate this h-chunk into output ----
        const float* w2p = W2e + (size_t)(ch * HC) * D_OUT + tid;
#pragma unroll 2
        for (int jj = 0; jj < HC; jj++) {
            float hv[BM];
#pragma unroll
            for (int t = 0; t < BM; t++) hv[t] = hs[t][jj];
#pragma unroll
            for (int c = 0; c < 4; c++) {
                float w2 = w2p[(size_t)jj * D_OUT + 256 * c];
#pragma unroll
                for (int t = 0; t < BM; t++) acc[t][c] += hv[t] * w2;
            }
        }
    }

    // scatter: out[token] += w * acc  (each token appears in exactly 2 buckets)
#pragma unroll
    for (int t = 0; t < BM; t++) {
        float w = wts[t];
        float* op = out + (size_t)toks[t] * D_OUT;
#pragma unroll
        for (int c = 0; c < 4; c++) atomicAdd(&op[tid + 256 * c], w * acc[t][c]);
    }
}

// ---------------- launcher ----------------
extern "C" void kernel_launch(void* const* d_in, const int* in_sizes, int n_in,
                              void* d_out, int out_size) {
    const float* x  = (const float*)d_in[0];
    const float* Wg = (const float*)d_in[1];
    const float* bg = (const float*)d_in[2];
    const float* W1 = (const float*)d_in[3];
    const float* b1 = (const float*)d_in[4];
    const float* W2 = (const float*)d_in[5];
    const float* b2 = (const float*)d_in[6];
    float* out = (float*)d_out;

    const int T = in_sizes[0] / D_IN;

    // zero the output (poisoned to 0xAA) and the routing counters
    cudaMemsetAsync(out, 0, (size_t)out_size * sizeof(float));
    zero_counts_kernel<<<1, 32>>>();

    // gating: 1 warp per token
    {
        int warps_per_block = NTHR / 32;
        int blocks = (T + warps_per_block - 1) / warps_per_block;
        gate_kernel<<<blocks, NTHR>>>(x, Wg, bg, T);
    }

    // grouped expert FFN
    {
        dim3 grid((T + BM - 1) / BM, E_EXP);
        ffn_kernel<<<grid, NTHR>>>(x, W1, b1, W2, b2, out);
    }
}

// round 4
// speedup vs baseline: 6.8385x; 6.8385x over previous
#include <cuda_runtime.h>
#include <cuda_bf16.h>
#include <math.h>
#include <stdint.h>

// Dims fixed by dataset: T=8192, E=8, D_IN=1024, D_H=4096, D_OUT=1024, TOP_K=2
#define E_EXP 8
#define DIN   1024
#define DH    4096
#define DOUT  1024
#define TMAXT 8192
#define SLOTS 16384
#define STAGES 4
#define GEMM_SMEM (STAGES * 32768)

// ---------------------------------------------------------------------------
__device__ __forceinline__ uint32_t smem_u32(const void* p) {
    uint32_t a;
    asm("{ .reg .u64 t; cvta.to.shared.u64 t, %1; cvt.u32.u64 %0, t; }" : "=r"(a) : "l"(p));
    return a;
}
__device__ __forceinline__ void cp16(uint32_t saddr, const void* gptr) {
    asm volatile("cp.async.cg.shared.global [%0], [%1], 16;" :: "r"(saddr), "l"(gptr) : "memory");
}
#define CP_COMMIT() asm volatile("cp.async.commit_group;" ::: "memory")
#define CP_WAIT(N)  asm volatile("cp.async.wait_group %0;" :: "n"(N) : "memory")

__device__ __forceinline__ void ldmx4(uint32_t* d, uint32_t addr) {
    asm volatile("ldmatrix.sync.aligned.m8n8.x4.shared.b16 {%0,%1,%2,%3}, [%4];"
                 : "=r"(d[0]), "=r"(d[1]), "=r"(d[2]), "=r"(d[3]) : "r"(addr));
}
__device__ __forceinline__ void mma_bf16(float* c, const uint32_t* a, const uint32_t* b) {
    asm volatile(
        "mma.sync.aligned.m16n8k16.row.col.f32.bf16.bf16.f32 "
        "{%0,%1,%2,%3}, {%4,%5,%6,%7}, {%8,%9}, {%0,%1,%2,%3};"
        : "+f"(c[0]), "+f"(c[1]), "+f"(c[2]), "+f"(c[3])
        : "r"(a[0]), "r"(a[1]), "r"(a[2]), "r"(a[3]), "r"(b[0]), "r"(b[1]));
}

// ---------------------------------------------------------------------------
// Device scratch (allocation-free)
// ---------------------------------------------------------------------------
__device__ int   g_counts[E_EXP];
__device__ int   g_hoff[E_EXP];
__device__ int   g_btok[E_EXP * TMAXT];
__device__ int   g_texp[TMAXT * 2];
__device__ int   g_tpos[TMAXT * 2];
__device__ float g_tw[TMAXT * 2];

__device__ __nv_bfloat16 g_W1c[(size_t)E_EXP * DH * (3 * DIN)];   // [e][n][k' = hi|lo|hi]
__device__ __nv_bfloat16 g_W2c[(size_t)E_EXP * DOUT * (3 * DH)];
__device__ __nv_bfloat16 g_xhi[(size_t)TMAXT * DIN];
__device__ __nv_bfloat16 g_xlo[(size_t)TMAXT * DIN];
__device__ __nv_bfloat16 g_Hhi[(size_t)SLOTS * DH];
__device__ __nv_bfloat16 g_Hlo[(size_t)SLOTS * DH];
__device__ float         g_Y[(size_t)SLOTS * DOUT];

// ---------------------------------------------------------------------------
__global__ void zero_counts_kernel() {
    if (threadIdx.x < E_EXP) g_counts[threadIdx.x] = 0;
}
__global__ void offsets_kernel() {
    if (threadIdx.x == 0) {
        int acc = 0;
        for (int e = 0; e < E_EXP; e++) { g_hoff[e] = acc; acc += g_counts[e]; }
    }
}
__global__ void xsplit_kernel(const float* __restrict__ x) {
    size_t i = ((size_t)blockIdx.x * blockDim.x + threadIdx.x) * 4;
    float4 v = *(const float4*)(x + i);
    __nv_bfloat16 h0 = __float2bfloat16(v.x), h1 = __float2bfloat16(v.y);
    __nv_bfloat16 h2 = __float2bfloat16(v.z), h3 = __float2bfloat16(v.w);
    g_xhi[i] = h0; g_xhi[i+1] = h1; g_xhi[i+2] = h2; g_xhi[i+3] = h3;
    g_xlo[i]   = __float2bfloat16(v.x - __bfloat162float(h0));
    g_xlo[i+1] = __float2bfloat16(v.y - __bfloat162float(h1));
    g_xlo[i+2] = __float2bfloat16(v.z - __bfloat162float(h2));
    g_xlo[i+3] = __float2bfloat16(v.w - __bfloat162float(h3));
}

// transpose + hi/lo split:  W1[e][k][n] -> g_W1c[e][n][{k(hi), DIN+k(lo), 2DIN+k(hi)}]
__global__ void convW1_kernel(const float* __restrict__ W1) {
    __shared__ float ts[32][33];
    int e = blockIdx.z;
    int n0 = blockIdx.x * 32, k0 = blockIdx.y * 32;
    int tx = threadIdx.x, ty = threadIdx.y;
    const float* src = W1 + (size_t)e * DIN * DH;
#pragma unroll
    for (int j = 0; j < 4; j++)
        ts[ty + 8 * j][tx] = src[(size_t)(k0 + ty + 8 * j) * DH + n0 + tx];
    __syncthreads();
    __nv_bfloat16* dst = g_W1c + (size_t)e * DH * (3 * DIN);
#pragma unroll
    for (int j = 0; j < 4; j++) {
        int n = n0 + ty + 8 * j, k = k0 + tx;
        float v = ts[tx][ty + 8 * j];
        __nv_bfloat16 h = __float2bfloat16(v);
        __nv_bfloat16 l = __float2bfloat16(v - __bfloat162float(h));
        size_t r = (size_t)n * (3 * DIN);
        dst[r + k] = h; dst[r + DIN + k] = l; dst[r + 2 * DIN + k] = h;
    }
}
__global__ void convW2_kernel(const float* __restrict__ W2) {
    __shared__ float ts[32][33];
    int e = blockIdx.z;
    int n0 = blockIdx.x * 32, k0 = blockIdx.y * 32;
    int tx = threadIdx.x, ty = threadIdx.y;
    const float* src = W2 + (size_t)e * DH * DOUT;
#pragma unroll
    for (int j = 0; j < 4; j++)
        ts[ty + 8 * j][tx] = src[(size_t)(k0 + ty + 8 * j) * DOUT + n0 + tx];
    __syncthreads();
    __nv_bfloat16* dst = g_W2c + (size_t)e * DOUT * (3 * DH);
#pragma unroll
    for (int j = 0; j < 4; j++) {
        int n = n0 + ty + 8 * j, k = k0 + tx;
        float v = ts[tx][ty + 8 * j];
        __nv_bfloat16 h = __float2bfloat16(v);
        __nv_bfloat16 l = __float2bfloat16(v - __bfloat162float(h));
        size_t r = (size_t)n * (3 * DH);
        dst[r + k] = h; dst[r + DH + k] = l; dst[r + 2 * DH + k] = h;
    }
}

// ---------------------------------------------------------------------------
__global__ void gate_kernel(const float* __restrict__ x,
                            const float* __restrict__ Wg,
                            const float* __restrict__ bg) {
    int t = (blockIdx.x * blockDim.x + threadIdx.x) >> 5;
    int lane = threadIdx.x & 31;
    if (t >= TMAXT) return;
    const float* xr = x + (size_t)t * DIN;
    float xv[32];
#pragma unroll
    for (int k = 0; k < 32; k++) xv[k] = xr[lane + 32 * k];
    float logit[E_EXP];
#pragma unroll
    for (int e = 0; e < E_EXP; e++) {
        float s = 0.f;
#pragma unroll
        for (int k = 0; k < 32; k++) s += xv[k] * Wg[(size_t)(lane + 32 * k) * E_EXP + e];
#pragma unroll
        for (int off = 16; off; off >>= 1) s += __shfl_xor_sync(0xFFFFFFFFu, s, off);
        logit[e] = s + bg[e];
    }
    if (lane == 0) {
        int i0 = 0; float v0 = logit[0];
#pragma unroll
        for (int e = 1; e < E_EXP; e++) if (logit[e] > v0) { v0 = logit[e]; i0 = e; }
        int i1 = -1; float v1 = -INFINITY;
#pragma unroll
        for (int e = 0; e < E_EXP; e++) if (e != i0 && logit[e] > v1) { v1 = logit[e]; i1 = e; }
        float e1 = expf(v1 - v0);
        float inv = 1.f / (1.f + e1);
        float w0 = inv, w1 = e1 * inv;
        int s0 = atomicAdd(&g_counts[i0], 1);
        g_btok[i0 * TMAXT + s0] = t;
        int s1 = atomicAdd(&g_counts[i1], 1);
        g_btok[i1 * TMAXT + s1] = t;
        g_texp[2 * t] = i0; g_tpos[2 * t] = s0; g_tw[2 * t] = w0;
        g_texp[2 * t + 1] = i1; g_tpos[2 * t + 1] = s1; g_tw[2 * t + 1] = w1;
    }
}

// ---------------------------------------------------------------------------
// grouped GEMM via mma.sync (m16n8k16 bf16), CTA tile 128x128, K-tile 64,
// 4-stage cp.async pipeline, SW128 swizzled smem, ldmatrix fragments.
// PHASE 1: A = x hi/lo (gather by token), B = W1c, epi = bias+relu+split -> H
// PHASE 2: A = H hi/lo,                   B = W2c, epi = bias -> Y (fp32)
// ---------------------------------------------------------------------------
template <int PHASE>
__global__ void __launch_bounds__(256, 1)
gemm_kernel(const float* __restrict__ bias_all) {
    constexpr int KTOT  = (PHASE == 1) ? 3 * DIN : 3 * DH;
    constexpr int KPART = KTOT / 3;
    constexpr int NFULL = (PHASE == 1) ? DH : DOUT;
    constexpr int ALD   = (PHASE == 1) ? DIN : DH;
    constexpr int NK    = KTOT / 64;

    const int e  = blockIdx.z;
    const int ne = g_counts[e];
    const int m0 = blockIdx.x * 128;
    if (m0 >= ne) return;
    const int n0 = blockIdx.y * 128;

    extern __shared__ char dsm[];
    __shared__ int rsrc[128];

    const int tid  = threadIdx.x;
    const int wid  = tid >> 5;
    const int lane = tid & 31;
    const int hoff = g_hoff[e];

    if (tid < 128) {
        int slot = min(m0 + tid, ne - 1);
        rsrc[tid] = (PHASE == 1) ? g_btok[e * TMAXT + slot] : (hoff + slot);
    }
    __syncthreads();

    const uint32_t sbase = smem_u32(dsm);
    const __nv_bfloat16* __restrict__ Ahi = (PHASE == 1) ? g_xhi : g_Hhi;
    const __nv_bfloat16* __restrict__ Alo = (PHASE == 1) ? g_xlo : g_Hlo;
    const __nv_bfloat16* __restrict__ Bexp =
        ((PHASE == 1) ? g_W1c : g_W2c) + (size_t)e * NFULL * KTOT;

    // ---- tile loader: 128 rows x 128 B for A and B each (swizzled) ----
    auto load_tile = [&](int it) {
        const int k0 = it * 64;
        const int p  = k0 / KPART;            // A parts: hi, hi, lo ; B: hi, lo, hi
        const int kk = k0 - p * KPART;
        const __nv_bfloat16* __restrict__ Asrc = (p < 2) ? Ahi : Alo;
        const uint32_t sA = sbase + (it % STAGES) * 32768;
        const uint32_t sB = sA + 16384;
#pragma unroll
        for (int j = 0; j < 4; j++) {
            int idx = tid + 256 * j;
            int row = idx >> 3, c16 = idx & 7;
            uint32_t soff = (uint32_t)(row << 7) | (uint32_t)((c16 ^ (row & 7)) << 4);
            cp16(sA + soff, Asrc + (size_t)rsrc[row] * ALD + kk + c16 * 8);
        }
#pragma unroll
        for (int j = 0; j < 4; j++) {
            int idx = tid + 256 * j;
            int row = idx >> 3, c16 = idx & 7;
            uint32_t soff = (uint32_t)(row << 7) | (uint32_t)((c16 ^ (row & 7)) << 4);
            cp16(sB + soff, Bexp + (size_t)(n0 + row) * KTOT + k0 + c16 * 8);
        }
        CP_COMMIT();
    };

    // warp tile: 32 (M) x 64 (N);  warps laid out 4 (M) x 2 (N)
    const int wm = wid & 3;
    const int wn = wid >> 2;

    float acc[2][8][4];
#pragma unroll
    for (int mt = 0; mt < 2; mt++)
#pragma unroll
        for (int no = 0; no < 8; no++)
#pragma unroll
            for (int q = 0; q < 4; q++) acc[mt][no][q] = 0.f;

    int fetch = 0;
    for (; fetch < STAGES - 1; fetch++) load_tile(fetch);

    for (int i = 0; i < NK; i++) {
        CP_WAIT(STAGES - 2);
        __syncthreads();
        if (fetch < NK) { load_tile(fetch); fetch++; }

        const uint32_t sA = sbase + (i % STAGES) * 32768;
        const uint32_t sB = sA + 16384;

#pragma unroll
        for (int kk = 0; kk < 4; kk++) {
            uint32_t a[2][4], b[8][2];
#pragma unroll
            for (int mt = 0; mt < 2; mt++) {
                int r  = wm * 32 + mt * 16 + (lane & 15);
                int ck = kk * 2 + (lane >> 4);          // 16B chunk index 0..7
                uint32_t addr = sA + (uint32_t)(r << 7) + (uint32_t)((ck ^ (r & 7)) << 4);
                ldmx4(a[mt], addr);
            }
#pragma unroll
            for (int nt = 0; nt < 4; nt++) {
                int r  = wn * 64 + nt * 16 + ((lane >> 4) << 3) + (lane & 7);
                int ck = kk * 2 + ((lane >> 3) & 1);
                uint32_t addr = sB + (uint32_t)(r << 7) + (uint32_t)((ck ^ (r & 7)) << 4);
                uint32_t bb[4];
                ldmx4(bb, addr);
                b[nt * 2][0] = bb[0]; b[nt * 2][1] = bb[1];
                b[nt * 2 + 1][0] = bb[2]; b[nt * 2 + 1][1] = bb[3];
            }
#pragma unroll
            for (int mt = 0; mt < 2; mt++)
#pragma unroll
                for (int no = 0; no < 8; no++)
                    mma_bf16(acc[mt][no], a[mt], b[no]);
        }
        __syncthreads();
    }

    // ---------------- epilogue ----------------
    const float* __restrict__ bias = bias_all + (size_t)e * NFULL;
#pragma unroll
    for (int mt = 0; mt < 2; mt++) {
#pragma unroll
        for (int no = 0; no < 8; no++) {
            int col = n0 + wn * 64 + no * 8 + (lane & 3) * 2;
            float bc0 = bias[col], bc1 = bias[col + 1];
#pragma unroll
            for (int h = 0; h < 2; h++) {
                int slot = m0 + wm * 32 + mt * 16 + (lane >> 2) + 8 * h;
                if (slot >= ne) continue;
                size_t drow = (size_t)(hoff + slot);
                float v0 = acc[mt][no][2 * h]     + bc0;
                float v1 = acc[mt][no][2 * h + 1] + bc1;
                if (PHASE == 1) {
                    v0 = fmaxf(v0, 0.f); v1 = fmaxf(v1, 0.f);
                    __nv_bfloat16 h0 = __float2bfloat16(v0);
                    __nv_bfloat16 h1 = __float2bfloat16(v1);
                    __nv_bfloat16 l0 = __float2bfloat16(v0 - __bfloat162float(h0));
                    __nv_bfloat16 l1 = __float2bfloat16(v1 - __bfloat162float(h1));
                    uint32_t hp = (uint32_t)__bfloat16_as_ushort(h0) |
                                  ((uint32_t)__bfloat16_as_ushort(h1) << 16);
                    uint32_t lp = (uint32_t)__bfloat16_as_ushort(l0) |
                                  ((uint32_t)__bfloat16_as_ushort(l1) << 16);
                    *(uint32_t*)(g_Hhi + drow * DH + col) = hp;
                    *(uint32_t*)(g_Hlo + drow * DH + col) = lp;
                } else {
                    float2 f = make_float2(v0, v1);
                    *(float2*)(g_Y + drow * DOUT + col) = f;
                }
            }
        }
    }
}

// ---------------------------------------------------------------------------
__global__ void combine_kernel(float* __restrict__ out) {
    int t = blockIdx.x;
    int c = threadIdx.x;
    int e0 = g_texp[2 * t], e1 = g_texp[2 * t + 1];
    size_t r0 = (size_t)(g_hoff[e0] + g_tpos[2 * t]);
    size_t r1 = (size_t)(g_hoff[e1] + g_tpos[2 * t + 1]);
    float w0 = g_tw[2 * t], w1 = g_tw[2 * t + 1];
    float4 y0 = ((const float4*)(g_Y + r0 * DOUT))[c];
    float4 y1 = ((const float4*)(g_Y + r1 * DOUT))[c];
    float4 o;
    o.x = w0 * y0.x + w1 * y1.x; o.y = w0 * y0.y + w1 * y1.y;
    o.z = w0 * y0.z + w1 * y1.z; o.w = w0 * y0.w + w1 * y1.w;
    ((float4*)(out + (size_t)t * DOUT))[c] = o;
}

// ---------------------------------------------------------------------------
extern "C" void kernel_launch(void* const* d_in, const int* in_sizes, int n_in,
                              void* d_out, int out_size) {
    const float* x  = (const float*)d_in[0];
    const float* Wg = (const float*)d_in[1];
    const float* bg = (const float*)d_in[2];
    const float* W1 = (const float*)d_in[3];
    const float* b1 = (const float*)d_in[4];
    const float* W2 = (const float*)d_in[5];
    const float* b2 = (const float*)d_in[6];
    float* out = (float*)d_out;

    static bool attr_done = false;
    if (!attr_done) {
        cudaFuncSetAttribute(gemm_kernel<1>, cudaFuncAttributeMaxDynamicSharedMemorySize, GEMM_SMEM);
        cudaFuncSetAttribute(gemm_kernel<2>, cudaFuncAttributeMaxDynamicSharedMemorySize, GEMM_SMEM);
        attr_done = true;
    }

    zero_counts_kernel<<<1, 32>>>();
    convW1_kernel<<<dim3(DH / 32, DIN / 32, E_EXP), dim3(32, 8)>>>(W1);
    convW2_kernel<<<dim3(DOUT / 32, DH / 32, E_EXP), dim3(32, 8)>>>(W2);
    xsplit_kernel<<<(TMAXT * DIN) / (256 * 4), 256>>>(x);
    gate_kernel<<<TMAXT / 8, 256>>>(x, Wg, bg);
    offsets_kernel<<<1, 32>>>();

    gemm_kernel<1><<<dim3(TMAXT / 128, DH / 128, E_EXP), 256, GEMM_SMEM>>>(b1);
    gemm_kernel<2><<<dim3(TMAXT / 128, DOUT / 128, E_EXP), 256, GEMM_SMEM>>>(b2);
    combine_kernel<<<TMAXT, 256>>>(out);
}

// round 13
// speedup vs baseline: 10.4682x; 1.5308x over previous
#include <cuda_runtime.h>
#include <cuda_fp16.h>
#include <math.h>
#include <stdint.h>

// Dims fixed by dataset: T=8192, E=8, D_IN=1024, D_H=4096, D_OUT=1024, TOP_K=2
#define E_EXP 8
#define DIN   1024
#define DH    4096
#define DOUT  1024
#define TMAXT 8192
#define SLOTS 16384
#define STAGES 4
#define GEMM_SMEM (STAGES * 32768)

// ---------------------------------------------------------------------------
__device__ __forceinline__ uint32_t smem_u32(const void* p) {
    uint32_t a;
    asm("{ .reg .u64 t; cvta.to.shared.u64 t, %1; cvt.u32.u64 %0, t; }" : "=r"(a) : "l"(p));
    return a;
}
__device__ __forceinline__ void cp16(uint32_t saddr, const void* gptr) {
    asm volatile("cp.async.cg.shared.global [%0], [%1], 16;" :: "r"(saddr), "l"(gptr) : "memory");
}
#define CP_COMMIT() asm volatile("cp.async.commit_group;" ::: "memory")
#define CP_WAIT(N)  asm volatile("cp.async.wait_group %0;" :: "n"(N) : "memory")

__device__ __forceinline__ void ldmx4(uint32_t* d, uint32_t addr) {
    asm volatile("ldmatrix.sync.aligned.m8n8.x4.shared.b16 {%0,%1,%2,%3}, [%4];"
                 : "=r"(d[0]), "=r"(d[1]), "=r"(d[2]), "=r"(d[3]) : "r"(addr));
}
__device__ __forceinline__ void mma_fp16(float* c, const uint32_t* a, const uint32_t* b) {
    asm volatile(
        "mma.sync.aligned.m16n8k16.row.col.f32.f16.f16.f32 "
        "{%0,%1,%2,%3}, {%4,%5,%6,%7}, {%8,%9}, {%0,%1,%2,%3};"
        : "+f"(c[0]), "+f"(c[1]), "+f"(c[2]), "+f"(c[3])
        : "r"(a[0]), "r"(a[1]), "r"(a[2]), "r"(a[3]), "r"(b[0]), "r"(b[1]));
}

// ---------------------------------------------------------------------------
// Device scratch (allocation-free)
// ---------------------------------------------------------------------------
__device__ int   g_counts[E_EXP];
__device__ int   g_hoff[E_EXP];
__device__ int   g_btok[E_EXP * TMAXT];
__device__ int   g_texp[TMAXT * 2];
__device__ int   g_tpos[TMAXT * 2];
__device__ float g_tw[TMAXT * 2];

__device__ __half g_W1c[(size_t)E_EXP * DH * (2 * DIN)];   // [e][n][k' = hi|lo]
__device__ __half g_W2c[(size_t)E_EXP * DOUT * (2 * DH)];
__device__ __half g_xh[(size_t)TMAXT * DIN];
__device__ __half g_Hh[(size_t)SLOTS * DH];
__device__ float  g_Y[(size_t)SLOTS * DOUT];

// ---------------------------------------------------------------------------
__global__ void zero_counts_kernel() {
    if (threadIdx.x < E_EXP) g_counts[threadIdx.x] = 0;
}
__global__ void offsets_kernel() {
    if (threadIdx.x == 0) {
        int acc = 0;
        for (int e = 0; e < E_EXP; e++) { g_hoff[e] = acc; acc += g_counts[e]; }
    }
}
__global__ void xconv_kernel(const float* __restrict__ x) {
    size_t i = ((size_t)blockIdx.x * blockDim.x + threadIdx.x) * 4;
    float4 v = *(const float4*)(x + i);
    *(__half2*)(g_xh + i)     = make_half2(__float2half(v.x), __float2half(v.y));
    *(__half2*)(g_xh + i + 2) = make_half2(__float2half(v.z), __float2half(v.w));
}

// transpose + fp16 hi/lo split:  W[e][k][n] -> dst[e][n][{k(hi), KD+k(lo)}]
// WHICH selects the destination INSIDE device code (device globals must not
// be passed as host-side kernel arguments — that was the round-7/8 bug).
template <int KD, int ND, int WHICH>
__global__ void convW_kernel(const float* __restrict__ W) {
    __shared__ float ts[32][33];
    int e = blockIdx.z;
    int n0 = blockIdx.x * 32, k0 = blockIdx.y * 32;
    int tx = threadIdx.x, ty = threadIdx.y;
    const float* src = W + (size_t)e * KD * ND;
#pragma unroll
    for (int j = 0; j < 4; j++)
        ts[ty + 8 * j][tx] = src[(size_t)(k0 + ty + 8 * j) * ND + n0 + tx];
    __syncthreads();
    __half* dst = ((WHICH == 1) ? g_W1c : g_W2c) + (size_t)e * ND * (2 * KD);
#pragma unroll
    for (int j = 0; j < 4; j++) {
        int n = n0 + ty + 8 * j, k = k0 + tx;
        float v = ts[tx][ty + 8 * j];
        __half h = __float2half(v);
        __half l = __float2half(v - __half2float(h));
        size_t r = (size_t)n * (2 * KD);
        dst[r + k] = h; dst[r + KD + k] = l;
    }
}

// ---------------------------------------------------------------------------
__global__ void gate_kernel(const float* __restrict__ x,
                            const float* __restrict__ Wg,
                            const float* __restrict__ bg) {
    int t = (blockIdx.x * blockDim.x + threadIdx.x) >> 5;
    int lane = threadIdx.x & 31;
    if (t >= TMAXT) return;
    const float* xr = x + (size_t)t * DIN;
    float xv[32];
#pragma unroll
    for (int k = 0; k < 32; k++) xv[k] = xr[lane + 32 * k];
    float logit[E_EXP];
#pragma unroll
    for (int e = 0; e < E_EXP; e++) {
        float s = 0.f;
#pragma unroll
        for (int k = 0; k < 32; k++) s += xv[k] * Wg[(size_t)(lane + 32 * k) * E_EXP + e];
#pragma unroll
        for (int off = 16; off; off >>= 1) s += __shfl_xor_sync(0xFFFFFFFFu, s, off);
        logit[e] = s + bg[e];
    }
    if (lane == 0) {
        int i0 = 0; float v0 = logit[0];
#pragma unroll
        for (int e = 1; e < E_EXP; e++) if (logit[e] > v0) { v0 = logit[e]; i0 = e; }
        int i1 = -1; float v1 = -INFINITY;
#pragma unroll
        for (int e = 0; e < E_EXP; e++) if (e != i0 && logit[e] > v1) { v1 = logit[e]; i1 = e; }
        float e1 = expf(v1 - v0);
        float inv = 1.f / (1.f + e1);
        float w0 = inv, w1 = e1 * inv;
        int s0 = atomicAdd(&g_counts[i0], 1);
        g_btok[i0 * TMAXT + s0] = t;
        int s1 = atomicAdd(&g_counts[i1], 1);
        g_btok[i1 * TMAXT + s1] = t;
        g_texp[2 * t] = i0; g_tpos[2 * t] = s0; g_tw[2 * t] = w0;
        g_texp[2 * t + 1] = i1; g_tpos[2 * t + 1] = s1; g_tw[2 * t + 1] = w1;
    }
}

// ---------------------------------------------------------------------------
// grouped GEMM via mma.sync (m16n8k16 fp16), CTA tile 128x128, K-tile 64,
// 4-stage cp.async pipeline, swizzled smem — round-4 structure verbatim.
// A' = [Ah | Ah] (loader wraps k), B' = [Bh | Bl].
// PHASE 1: A = xh (gather by token), B = W1c, epi = bias+relu -> Hh (fp16)
// PHASE 2: A = Hh,                   B = W2c, epi = bias -> Y (fp32)
// ---------------------------------------------------------------------------
template <int PHASE>
__global__ void __launch_bounds__(256, 1)
gemm_kernel(const float* __restrict__ bias_all) {
    constexpr int KPART = (PHASE == 1) ? DIN : DH;
    constexpr int KTOT  = 2 * KPART;
    constexpr int NFULL = (PHASE == 1) ? DH : DOUT;
    constexpr int NK    = KTOT / 64;

    const int e  = blockIdx.z;
    const int ne = g_counts[e];
    const int m0 = blockIdx.x * 128;
    if (m0 >= ne) return;
    const int n0 = blockIdx.y * 128;

    extern __shared__ char dsm[];
    __shared__ int rsrc[128];

    const int tid  = threadIdx.x;
    const int wid  = tid >> 5;
    const int lane = tid & 31;
    const int hoff = g_hoff[e];

    if (tid < 128) {
        int slot = min(m0 + tid, ne - 1);
        rsrc[tid] = (PHASE == 1) ? g_btok[e * TMAXT + slot] : (hoff + slot);
    }
    __syncthreads();

    const uint32_t sbase = smem_u32(dsm);
    const __half* __restrict__ Ah = (PHASE == 1) ? g_xh : g_Hh;
    const __half* __restrict__ Bexp =
        ((PHASE == 1) ? g_W1c : g_W2c) + (size_t)e * NFULL * KTOT;

    // ---- tile loader: 128 rows x 128 B for A and B each (swizzled) ----
    auto load_tile = [&](int it) {
        const int k0 = it * 64;
        const int ka = (k0 >= KPART) ? k0 - KPART : k0;   // A wraps (hi twice)
        const uint32_t sA = sbase + (it % STAGES) * 32768;
        const uint32_t sB = sA + 16384;
#pragma unroll
        for (int j = 0; j < 4; j++) {
            int idx = tid + 256 * j;
            int row = idx >> 3, c16 = idx & 7;
            uint32_t soff = (uint32_t)(row << 7) | (uint32_t)((c16 ^ (row & 7)) << 4);
            cp16(sA + soff, Ah + (size_t)rsrc[row] * KPART + ka + c16 * 8);
        }
#pragma unroll
        for (int j = 0; j < 4; j++) {
            int idx = tid + 256 * j;
            int row = idx >> 3, c16 = idx & 7;
            uint32_t soff = (uint32_t)(row << 7) | (uint32_t)((c16 ^ (row & 7)) << 4);
            cp16(sB + soff, Bexp + (size_t)(n0 + row) * KTOT + k0 + c16 * 8);
        }
        CP_COMMIT();
    };

    // warp tile: 32 (M) x 64 (N);  warps laid out 4 (M) x 2 (N)
    const int wm = wid & 3;
    const int wn = wid >> 2;

    float acc[2][8][4];
#pragma unroll
    for (int mt = 0; mt < 2; mt++)
#pragma unroll
        for (int no = 0; no < 8; no++)
#pragma unroll
            for (int q = 0; q < 4; q++) acc[mt][no][q] = 0.f;

    int fetch = 0;
    for (; fetch < STAGES - 1; fetch++) load_tile(fetch);

    for (int i = 0; i < NK; i++) {
        CP_WAIT(STAGES - 2);
        __syncthreads();
        if (fetch < NK) { load_tile(fetch); fetch++; }
        else            { CP_COMMIT(); }   // keep group count advancing for tail

        const uint32_t sA = sbase + (i % STAGES) * 32768;
        const uint32_t sB = sA + 16384;

#pragma unroll
        for (int kk = 0; kk < 4; kk++) {
            uint32_t a[2][4], b[8][2];
#pragma unroll
            for (int mt = 0; mt < 2; mt++) {
                int r  = wm * 32 + mt * 16 + (lane & 15);
                int ck = kk * 2 + (lane >> 4);          // 16B chunk index 0..7
                uint32_t addr = sA + (uint32_t)(r << 7) + (uint32_t)((ck ^ (r & 7)) << 4);
                ldmx4(a[mt], addr);
            }
#pragma unroll
            for (int nt = 0; nt < 4; nt++) {
                int r  = wn * 64 + nt * 16 + ((lane >> 4) << 3) + (lane & 7);
                int ck = kk * 2 + ((lane >> 3) & 1);
                uint32_t addr = sB + (uint32_t)(r << 7) + (uint32_t)((ck ^ (r & 7)) << 4);
                uint32_t bb[4];
                ldmx4(bb, addr);
                b[nt * 2][0] = bb[0]; b[nt * 2][1] = bb[1];
                b[nt * 2 + 1][0] = bb[2]; b[nt * 2 + 1][1] = bb[3];
            }
#pragma unroll
            for (int mt = 0; mt < 2; mt++)
#pragma unroll
                for (int no = 0; no < 8; no++)
                    mma_fp16(acc[mt][no], a[mt], b[no]);
        }
        __syncthreads();
    }

    // ---------------- epilogue ----------------
    const float* __restrict__ bias = bias_all + (size_t)e * NFULL;
#pragma unroll
    for (int mt = 0; mt < 2; mt++) {
#pragma unroll
        for (int no = 0; no < 8; no++) {
            int col = n0 + wn * 64 + no * 8 + (lane & 3) * 2;
            float bc0 = bias[col], bc1 = bias[col + 1];
#pragma unroll
            for (int h = 0; h < 2; h++) {
                int slot = m0 + wm * 32 + mt * 16 + (lane >> 2) + 8 * h;
                if (slot >= ne) continue;
                size_t drow = (size_t)(hoff + slot);
                float v0 = acc[mt][no][2 * h]     + bc0;
                float v1 = acc[mt][no][2 * h + 1] + bc1;
                if (PHASE == 1) {
                    v0 = fmaxf(v0, 0.f); v1 = fmaxf(v1, 0.f);
                    *(__half2*)(g_Hh + drow * DH + col) =
                        make_half2(__float2half(v0), __float2half(v1));
                } else {
                    *(float2*)(g_Y + drow * DOUT + col) = make_float2(v0, v1);
                }
            }
        }
    }
}

// ---------------------------------------------------------------------------
__global__ void combine_kernel(float* __restrict__ out) {
    int t = blockIdx.x;
    int c = threadIdx.x;
    int e0 = g_texp[2 * t], e1 = g_texp[2 * t + 1];
    size_t r0 = (size_t)(g_hoff[e0] + g_tpos[2 * t]);
    size_t r1 = (size_t)(g_hoff[e1] + g_tpos[2 * t + 1]);
    float w0 = g_tw[2 * t], w1 = g_tw[2 * t + 1];
    float4 y0 = ((const float4*)(g_Y + r0 * DOUT))[c];
    float4 y1 = ((const float4*)(g_Y + r1 * DOUT))[c];
    float4 o;
    o.x = w0 * y0.x + w1 * y1.x; o.y = w0 * y0.y + w1 * y1.y;
    o.z = w0 * y0.z + w1 * y1.z; o.w = w0 * y0.w + w1 * y1.w;
    ((float4*)(out + (size_t)t * DOUT))[c] = o;
}

// ---------------------------------------------------------------------------
extern "C" void kernel_launch(void* const* d_in, const int* in_sizes, int n_in,
                              void* d_out, int out_size) {
    const float* x  = (const float*)d_in[0];
    const float* Wg = (const float*)d_in[1];
    const float* bg = (const float*)d_in[2];
    const float* W1 = (const float*)d_in[3];
    const float* b1 = (const float*)d_in[4];
    const float* W2 = (const float*)d_in[5];
    const float* b2 = (const float*)d_in[6];
    float* out = (float*)d_out;

    static bool attr_done = false;
    if (!attr_done) {
        cudaFuncSetAttribute(gemm_kernel<1>, cudaFuncAttributeMaxDynamicSharedMemorySize, GEMM_SMEM);
        cudaFuncSetAttribute(gemm_kernel<2>, cudaFuncAttributeMaxDynamicSharedMemorySize, GEMM_SMEM);
        attr_done = true;
    }

    zero_counts_kernel<<<1, 32>>>();
    convW_kernel<DIN, DH, 1><<<dim3(DH / 32, DIN / 32, E_EXP), dim3(32, 8)>>>(W1);
    convW_kernel<DH, DOUT, 2><<<dim3(DOUT / 32, DH / 32, E_EXP), dim3(32, 8)>>>(W2);
    xconv_kernel<<<(TMAXT * DIN) / (256 * 4), 256>>>(x);
    gate_kernel<<<TMAXT / 8, 256>>>(x, Wg, bg);
    offsets_kernel<<<1, 32>>>();

    gemm_kernel<1><<<dim3(TMAXT / 128, DH / 128, E_EXP), 256, GEMM_SMEM>>>(b1);
    gemm_kernel<2><<<dim3(TMAXT / 128, DOUT / 128, E_EXP), 256, GEMM_SMEM>>>(b2);
    combine_kernel<<<TMAXT, 256>>>(out);
}